// round 9
// baseline (speedup 1.0000x reference)
#include <cuda_runtime.h>
#include <cuda_fp16.h>

#define DIMD 33
#define H_ORG 2160
#define W_ORG 3840
#define HW (H_ORG * W_ORG)          // 8294400
#define LUTN (DIMD * DIMD * DIMD)   // 35937
#define NPIX 65536                  // 256*256 small image
#define NFEAT 10
#define NBLK_FEAT 256
#define NPVAL (3 * 5 * 1089)        // 16335
#define NLBLK 141                   // ceil(LUTN/256)

// ---- device scratch (no allocations allowed) ----
__device__ float    g_partials[NBLK_FEAT * NFEAT];
__device__ float    g_P[NPVAL];          // P[ch][s][q]
__device__ unsigned g_PmaxU[15];         // per-(ch,s) max |P| as uint bits
__device__ float    g_gs;                // global quant scale (bound/511)
__device__ unsigned g_lutS32[LUTN];      // 3x10-bit fixed point, global scale

// ============================================================
// Kernel A: gather features, block-reduce partial sums (deterministic)
// Also resets g_PmaxU for this launch (stream-ordered before bwp).
// ============================================================
__global__ void feat_kernel(const int* __restrict__ msb, const int* __restrict__ lsb,
                            const float* __restrict__ fm, const float* __restrict__ fl) {
    if (blockIdx.x == 0 && threadIdx.x < 15) g_PmaxU[threadIdx.x] = 0u;

    int pid = blockIdx.x * 256 + threadIdx.x;

    int imr = msb[pid], img = msb[pid + NPIX], imb = msb[pid + 2 * NPIX];
    int ilr = lsb[pid], ilg = lsb[pid + NPIX], ilb = lsb[pid + 2 * NPIX];
    long imx = (long)(imr * 4096 + img * 256 + imb * 16) * NFEAT;
    long ilx = (long)(ilr * 4096 + ilg * 256 + ilb * 16) * NFEAT;

    const float4* fm4 = (const float4*)(fm + imx);
    const float4* fl4 = (const float4*)(fl + ilx);
    float4 a0 = __ldg(&fm4[0]), a1 = __ldg(&fm4[1]);
    float2 a2 = __ldg((const float2*)(fm + imx + 8));
    float4 b0 = __ldg(&fl4[0]), b1 = __ldg(&fl4[1]);
    float2 b2 = __ldg((const float2*)(fl + ilx + 8));

    float acc[NFEAT];
    acc[0] = a0.x + b0.x; acc[1] = a0.y + b0.y;
    acc[2] = a0.z + b0.z; acc[3] = a0.w + b0.w;
    acc[4] = a1.x + b1.x; acc[5] = a1.y + b1.y;
    acc[6] = a1.z + b1.z; acc[7] = a1.w + b1.w;
    acc[8] = a2.x + b2.x; acc[9] = a2.y + b2.y;

#pragma unroll
    for (int f = 0; f < NFEAT; f++) {
#pragma unroll
        for (int o = 16; o > 0; o >>= 1)
            acc[f] += __shfl_down_sync(0xffffffffu, acc[f], o);
    }

    __shared__ float sw[8][NFEAT];
    int warp = threadIdx.x >> 5, lane = threadIdx.x & 31;
    if (lane == 0) {
#pragma unroll
        for (int f = 0; f < NFEAT; f++) sw[warp][f] = acc[f];
    }
    __syncthreads();
    if (threadIdx.x == 0) {
#pragma unroll
        for (int f = 0; f < NFEAT; f++) {
            float s = 0.f;
#pragma unroll
            for (int w = 0; w < 8; w++) s += sw[w][f];
            g_partials[blockIdx.x * NFEAT + f] = s;
        }
    }
}

// ============================================================
// Kernel B: fused bweights + P (each block redundantly computes Q)
// + per-(ch,s) |P| max via smem+global atomicMax (deterministic)
// ============================================================
__global__ void bwp_kernel(const float* __restrict__ lut_cat,
                           const float* __restrict__ luts,
                           const float* __restrict__ w_layers) {
    __shared__ int      smid[NFEAT];
    __shared__ float    swt[NFEAT];
    __shared__ float    sQ[150];
    __shared__ unsigned sMax[15];
    int t = threadIdx.x;

    if (t < 15) sMax[t] = 0u;
    if (t < NFEAT) {
        float s = 0.f;
        for (int b = 0; b < NBLK_FEAT; b++) s += g_partials[b * NFEAT + t];
        float pooled = s * (1.0f / (float)NPIX);
        float p = rintf(pooled * 2.0f) * 0.5f;      // round half-even like jnp.round
        p = fminf(fmaxf(p, -16.0f), 15.5f);
        smid[t] = (int)(p * 2.0f) + 32;
    }
    __syncthreads();
    if (t < NFEAT) {
        float w = 0.f;
#pragma unroll
        for (int i = 0; i < 5; i++) {
            int index = smid[2 * i] * 64 + smid[2 * i + 1];
            w += (lut_cat[(i * 4096 + index) * NFEAT + t] - 32.0f) * 0.25f;
        }
        swt[t] = w;
    }
    __syncthreads();
    if (t < 150) {
        int ch = t / 50, s = (t / 10) % 5, w = t % 10;
        float q = 0.f;
#pragma unroll
        for (int n = 0; n < NFEAT; n++)
            q += swt[n] * luts[(s * 30 + 3 * n + ch) * NFEAT + w];
        sQ[t] = q;
    }
    __syncthreads();

    int idx = blockIdx.x * 256 + t;
    if (idx < NPVAL) {
        int chs = idx / 1089;
        int q   = idx % 1089;
        float p = 0.f;
#pragma unroll
        for (int w = 0; w < 10; w++)
            p += sQ[chs * 10 + w] * __ldg(&w_layers[w * 1089 + q]);
        g_P[idx] = p;
        atomicMax(&sMax[chs], __float_as_uint(fabsf(p)));   // |p| >= 0: uint cmp == float cmp
    }
    __syncthreads();
    if (t < 15 && sMax[t] != 0u) atomicMax(&g_PmaxU[t], sMax[t]);
}

// ============================================================
// Kernel B2: final fp32 LUT -> d3lut output + fused 10-bit quantize.
// Scale from analytic bound: |L_ch(x)| <= sum_s |sl[x,s]|*Pmax[ch,s];
// every block computes the identical bound bit-exactly.
// ============================================================
__global__ void lut_final_kernel(const float* __restrict__ s_layers,
                                 float* __restrict__ out_lut) {
    extern __shared__ float s_P[];           // NPVAL floats (65340 B)
    __shared__ float s_sl[DIMD * 5];
    __shared__ float s_pm[15];
    __shared__ float s_bx[DIMD];
    __shared__ float s_scale[2];             // [0]=inv, [1]=gs

    int t = threadIdx.x;
    if (t < DIMD * 5) s_sl[t] = s_layers[t];
    if (t < 15) s_pm[t] = __uint_as_float(g_PmaxU[t]);
    for (int i = t; i < NPVAL; i += 256) s_P[i] = g_P[i];
    __syncthreads();

    if (t < DIMD) {
        float bx = 0.f;
#pragma unroll
        for (int ch = 0; ch < 3; ch++) {
            float b = 0.f;
#pragma unroll
            for (int s = 0; s < 5; s++)
                b += fabsf(s_sl[t * 5 + s]) * s_pm[ch * 5 + s];
            bx = fmaxf(bx, b);
        }
        s_bx[t] = bx;
    }
    __syncthreads();
    if (t == 0) {
        float bound = s_bx[0];
        for (int x = 1; x < DIMD; x++) bound = fmaxf(bound, s_bx[x]);
        bound = fmaxf(bound, 1e-20f);
        float gs = bound * (1.0f / 511.0f);
        s_scale[0] = 1.0f / gs;
        s_scale[1] = gs;
        if (blockIdx.x == 0) g_gs = gs;
    }
    __syncthreads();
    float inv = s_scale[0];

    int v = blockIdx.x * 256 + t;
    if (v >= LUTN) return;
    int b = v / 1089;
    int g = (v / 33) % 33;
    int r = v % 33;
    int qr = b * 33 + g, qg = b * 33 + r, qb = g * 33 + r;
    float Lr = 0.f, Lg = 0.f, Lb = 0.f;
#pragma unroll
    for (int s = 0; s < 5; s++) {
        Lr += s_sl[r * 5 + s] * s_P[(0 * 5 + s) * 1089 + qr];
        Lg += s_sl[g * 5 + s] * s_P[(1 * 5 + s) * 1089 + qg];
        Lb += s_sl[b * 5 + s] * s_P[(2 * 5 + s) * 1089 + qb];
    }
    out_lut[v]            = Lr;
    out_lut[LUTN + v]     = Lg;
    out_lut[2 * LUTN + v] = Lb;

    unsigned mR = (unsigned)((int)rintf(Lr * inv) + 512);
    unsigned mG = (unsigned)((int)rintf(Lg * inv) + 512);
    unsigned mB = (unsigned)((int)rintf(Lb * inv) + 512);
    g_lutS32[v] = (mB << 2) | (mG << 12) | (mR << 22);
}

// ============================================================
// Kernel C: persistent trilinear apply; LUT in smem, 10-bit decode
// ============================================================
#define APPLY_BLOCKS 148
#define APPLY_THREADS 1024
#define NG (HW / 4)   // 2073600 float4 pixel-groups

__device__ __forceinline__ void corner_acc(unsigned u, float w,
                                           float& aR, float& aG, float& aB) {
    float fG = __uint_as_float((u & 0x003FF000u) | 0x3F800000u);          // 1 + mG/2048
    float fR = __uint_as_float(((u >> 10) & 0x003FF000u) | 0x3F800000u);  // 1 + mR/2048
    float fB = __uint_as_float(((u << 10) & 0x003FF000u) | 0x3F800000u);  // 1 + mB/2048
    aR = fmaf(w, fR, aR);
    aG = fmaf(w, fG, aG);
    aB = fmaf(w, fB, aB);
}

__global__ void __launch_bounds__(APPLY_THREADS, 1)
apply_kernel(const float* __restrict__ img, float* __restrict__ out) {
    extern __shared__ unsigned s_lut[];

    for (int i = threadIdx.x; i < LUTN; i += APPLY_THREADS)
        s_lut[i] = g_lutS32[i];

    float GS = g_gs;
    float A = 2048.0f * GS;     // Sum(w*f) = 1 + M/2048  ->  val = Sum*A - 2560*GS
    float C = 2560.0f * GS;
    __syncthreads();

    const float4* R = (const float4*)(img);
    const float4* G = (const float4*)(img + HW);
    const float4* B = (const float4*)(img + 2 * HW);
    float4* OR = (float4*)(out);
    float4* OG = (float4*)(out + HW);
    float4* OB = (float4*)(out + 2 * HW);

    const float inv_binsize = (float)((DIMD - 1) / 1.000001);

    for (int i = blockIdx.x * APPLY_THREADS + threadIdx.x; i < NG;
         i += APPLY_BLOCKS * APPLY_THREADS) {
        float4 r4 = __ldg(&R[i]), g4 = __ldg(&G[i]), b4 = __ldg(&B[i]);

        float rr[4] = {r4.x, r4.y, r4.z, r4.w};
        float gg[4] = {g4.x, g4.y, g4.z, g4.w};
        float bb[4] = {b4.x, b4.y, b4.z, b4.w};
        float ro[4], go[4], bo[4];

#pragma unroll
        for (int k = 0; k < 4; k++) {
            float rf = rr[k] * inv_binsize;
            float gf = gg[k] * inv_binsize;
            float bf = bb[k] * inv_binsize;
            int rid0 = (int)rf, gid0 = (int)gf, bid0 = (int)bf;   // floor (inputs >= 0)
            float rd = rf - (float)rid0;
            float gd = gf - (float)gid0;
            float bd = bf - (float)bid0;
            int rid = min(rid0, DIMD - 2);
            int gid = min(gid0, DIMD - 2);
            int bid = min(bid0, DIMD - 2);

            int base = (bid * 33 + gid) * 33 + rid;

            float g0 = 1.0f - gd;
            float r1g0 = rd * g0;
            float r0g0 = g0 - r1g0;
            float r1g1 = rd * gd;
            float r0g1 = gd - r1g1;
            float b0 = 1.0f - bd;
            float w000 = r0g0 * b0, w001 = r1g0 * b0;
            float w010 = r0g1 * b0, w011 = r1g1 * b0;
            float w100 = r0g0 * bd, w101 = r1g0 * bd;
            float w110 = r0g1 * bd, w111 = r1g1 * bd;

            float aR = 0.f, aG = 0.f, aB = 0.f;
            corner_acc(s_lut[base],        w000, aR, aG, aB);
            corner_acc(s_lut[base + 1],    w001, aR, aG, aB);
            corner_acc(s_lut[base + 33],   w010, aR, aG, aB);
            corner_acc(s_lut[base + 34],   w011, aR, aG, aB);
            corner_acc(s_lut[base + 1089], w100, aR, aG, aB);
            corner_acc(s_lut[base + 1090], w101, aR, aG, aB);
            corner_acc(s_lut[base + 1122], w110, aR, aG, aB);
            corner_acc(s_lut[base + 1123], w111, aR, aG, aB);

            ro[k] = fmaf(aR, A, rr[k] - C);
            go[k] = fmaf(aG, A, gg[k] - C);
            bo[k] = fmaf(aB, A, bb[k] - C);
        }

        OR[i] = make_float4(ro[0], ro[1], ro[2], ro[3]);
        OG[i] = make_float4(go[0], go[1], go[2], go[3]);
        OB[i] = make_float4(bo[0], bo[1], bo[2], bo[3]);
    }
}

// ============================================================
extern "C" void kernel_launch(void* const* d_in, const int* in_sizes, int n_in,
                              void* d_out, int out_size) {
    const int*   msb      = (const int*)d_in[0];
    const int*   lsb      = (const int*)d_in[1];
    const float* img      = (const float*)d_in[2];
    const float* fm       = (const float*)d_in[3];
    const float* fl       = (const float*)d_in[4];
    const float* lut_cat  = (const float*)d_in[5];
    const float* s_layers = (const float*)d_in[6];
    const float* w_layers = (const float*)d_in[7];
    const float* luts     = (const float*)d_in[8];
    float* out = (float*)d_out;

    const int apply_smem = LUTN * 4;          // 143748
    const int lutf_smem  = NPVAL * 4;         // 65340
    cudaFuncSetAttribute(apply_kernel, cudaFuncAttributeMaxDynamicSharedMemorySize,
                         apply_smem);
    cudaFuncSetAttribute(lut_final_kernel, cudaFuncAttributeMaxDynamicSharedMemorySize,
                         lutf_smem);

    feat_kernel<<<NBLK_FEAT, 256>>>(msb, lsb, fm, fl);
    bwp_kernel<<<(NPVAL + 255) / 256, 256>>>(lut_cat, luts, w_layers);
    lut_final_kernel<<<NLBLK, 256, lutf_smem>>>(s_layers, out + 3 * HW);
    apply_kernel<<<APPLY_BLOCKS, APPLY_THREADS, apply_smem>>>(img, out);
}

// round 10
// speedup vs baseline: 1.0940x; 1.0940x over previous
#include <cuda_runtime.h>
#include <cuda_fp16.h>

#define DIMD 33
#define H_ORG 2160
#define W_ORG 3840
#define HW (H_ORG * W_ORG)          // 8294400
#define LUTN (DIMD * DIMD * DIMD)   // 35937
#define NPIX 65536                  // 256*256 small image
#define NFEAT 10
#define NBLK_FEAT 256
#define NPVAL (3 * 5 * 1089)        // 16335
#define NLBLK 141                   // ceil(LUTN/256)

// ---- device scratch (no allocations allowed) ----
__device__ float    g_partials[NBLK_FEAT * NFEAT];
__device__ float    g_P[NPVAL];          // P[ch][s][q]
__device__ unsigned g_lutS32[LUTN];      // per-cell {m0,m1,m2, E}: int8 bias-128 + pow2 exp

// ============================================================
// Kernel A: gather features, block-reduce partial sums (deterministic)
// ============================================================
__global__ void feat_kernel(const int* __restrict__ msb, const int* __restrict__ lsb,
                            const float* __restrict__ fm, const float* __restrict__ fl) {
    int pid = blockIdx.x * 256 + threadIdx.x;

    int imr = msb[pid], img = msb[pid + NPIX], imb = msb[pid + 2 * NPIX];
    int ilr = lsb[pid], ilg = lsb[pid + NPIX], ilb = lsb[pid + 2 * NPIX];
    long imx = (long)(imr * 4096 + img * 256 + imb * 16) * NFEAT;
    long ilx = (long)(ilr * 4096 + ilg * 256 + ilb * 16) * NFEAT;

    const float4* fm4 = (const float4*)(fm + imx);
    const float4* fl4 = (const float4*)(fl + ilx);
    float4 a0 = __ldg(&fm4[0]), a1 = __ldg(&fm4[1]);
    float2 a2 = __ldg((const float2*)(fm + imx + 8));
    float4 b0 = __ldg(&fl4[0]), b1 = __ldg(&fl4[1]);
    float2 b2 = __ldg((const float2*)(fl + ilx + 8));

    float acc[NFEAT];
    acc[0] = a0.x + b0.x; acc[1] = a0.y + b0.y;
    acc[2] = a0.z + b0.z; acc[3] = a0.w + b0.w;
    acc[4] = a1.x + b1.x; acc[5] = a1.y + b1.y;
    acc[6] = a1.z + b1.z; acc[7] = a1.w + b1.w;
    acc[8] = a2.x + b2.x; acc[9] = a2.y + b2.y;

#pragma unroll
    for (int f = 0; f < NFEAT; f++) {
#pragma unroll
        for (int o = 16; o > 0; o >>= 1)
            acc[f] += __shfl_down_sync(0xffffffffu, acc[f], o);
    }

    __shared__ float sw[8][NFEAT];
    int warp = threadIdx.x >> 5, lane = threadIdx.x & 31;
    if (lane == 0) {
#pragma unroll
        for (int f = 0; f < NFEAT; f++) sw[warp][f] = acc[f];
    }
    __syncthreads();
    if (threadIdx.x == 0) {
#pragma unroll
        for (int f = 0; f < NFEAT; f++) {
            float s = 0.f;
#pragma unroll
            for (int w = 0; w < 8; w++) s += sw[w][f];
            g_partials[blockIdx.x * NFEAT + f] = s;
        }
    }
}

// ============================================================
// Kernel B: fused bweights + P (each block redundantly computes Q)
// ============================================================
__global__ void bwp_kernel(const float* __restrict__ lut_cat,
                           const float* __restrict__ luts,
                           const float* __restrict__ w_layers) {
    __shared__ int   smid[NFEAT];
    __shared__ float swt[NFEAT];
    __shared__ float sQ[150];
    int t = threadIdx.x;

    if (t < NFEAT) {
        float s = 0.f;
        for (int b = 0; b < NBLK_FEAT; b++) s += g_partials[b * NFEAT + t];
        float pooled = s * (1.0f / (float)NPIX);
        float p = rintf(pooled * 2.0f) * 0.5f;      // round half-even like jnp.round
        p = fminf(fmaxf(p, -16.0f), 15.5f);
        smid[t] = (int)(p * 2.0f) + 32;
    }
    __syncthreads();
    if (t < NFEAT) {
        float w = 0.f;
#pragma unroll
        for (int i = 0; i < 5; i++) {
            int index = smid[2 * i] * 64 + smid[2 * i + 1];
            w += (lut_cat[(i * 4096 + index) * NFEAT + t] - 32.0f) * 0.25f;
        }
        swt[t] = w;
    }
    __syncthreads();
    if (t < 150) {
        int ch = t / 50, s = (t / 10) % 5, w = t % 10;
        float q = 0.f;
#pragma unroll
        for (int n = 0; n < NFEAT; n++)
            q += swt[n] * luts[(s * 30 + 3 * n + ch) * NFEAT + w];
        sQ[t] = q;
    }
    __syncthreads();

    int idx = blockIdx.x * 256 + t;
    if (idx >= NPVAL) return;
    int chs = idx / 1089;
    int q   = idx % 1089;
    float p = 0.f;
#pragma unroll
    for (int w = 0; w < 10; w++)
        p += sQ[chs * 10 + w] * __ldg(&w_layers[w * 1089 + q]);
    g_P[idx] = p;
}

// ============================================================
// Kernel B2: final fp32 LUT (P preloaded in smem) -> d3lut output
// + fused per-cell int8/pow2 quantize (no global reduce needed).
// cell word: byte0..2 = round(val/scale)+128, byte3 = E (scale = 2^(E-127)),
// scale chosen so cellmax/scale in [64,128)
// ============================================================
__global__ void lut_final_kernel(const float* __restrict__ s_layers,
                                 float* __restrict__ out_lut) {
    extern __shared__ float s_P[];           // NPVAL floats (65340 B)
    __shared__ float s_sl[DIMD * 5];
    int t = threadIdx.x;
    if (t < DIMD * 5) s_sl[t] = s_layers[t];
    for (int i = t; i < NPVAL; i += 256) s_P[i] = g_P[i];
    __syncthreads();

    int v = blockIdx.x * 256 + t;
    if (v >= LUTN) return;
    int b = v / 1089;
    int g = (v / 33) % 33;
    int r = v % 33;
    int qr = b * 33 + g, qg = b * 33 + r, qb = g * 33 + r;
    float Lr = 0.f, Lg = 0.f, Lb = 0.f;
#pragma unroll
    for (int s = 0; s < 5; s++) {
        Lr += s_sl[r * 5 + s] * s_P[(0 * 5 + s) * 1089 + qr];
        Lg += s_sl[g * 5 + s] * s_P[(1 * 5 + s) * 1089 + qg];
        Lb += s_sl[b * 5 + s] * s_P[(2 * 5 + s) * 1089 + qb];
    }
    out_lut[v]            = Lr;
    out_lut[LUTN + v]     = Lg;
    out_lut[2 * LUTN + v] = Lb;

    float cellmax = fmaxf(fmaxf(fabsf(Lr), fabsf(Lg)), fmaxf(fabsf(Lb), 1e-20f));
    unsigned eu = (__float_as_uint(cellmax) >> 23) & 0xFF;   // floor exponent (biased)
    unsigned E  = eu - 6;                                    // scale = 2^(e-6) -> max/scale in [64,128)
    float inv   = __uint_as_float((254u - E) << 23);         // exact 1/scale (pow2)

    int m0 = min((int)rintf(Lr * inv), 127) + 128;
    int m1 = min((int)rintf(Lg * inv), 127) + 128;
    int m2 = min((int)rintf(Lb * inv), 127) + 128;
    g_lutS32[v] = (unsigned)m0 | ((unsigned)m1 << 8) | ((unsigned)m2 << 16) | (E << 24);
}

// ============================================================
// Kernel C: persistent trilinear apply; whole LUT in shared memory
// (proven R7 decode: prmt->half, per-cell pow2 scale, -1152*S2 fold)
// ============================================================
#define APPLY_BLOCKS 148
#define APPLY_THREADS 1024
#define NG (HW / 4)   // 2073600 float4 pixel-groups

__device__ __forceinline__ void corner_acc(unsigned u, float w,
                                           float& S1r, float& S1g, float& S1b, float& S2) {
    unsigned h01 = __byte_perm(u, 0x64646464u, 0x4140);  // halves: 1024+m0, 1024+m1
    unsigned h2  = __byte_perm(u, 0x64646464u, 0x4442);  // low half: 1024+m2
    float s  = __uint_as_float((u & 0xFF000000u) >> 1);  // 2^(E-127)
    float ws = w * s;
    float2 f01 = __half22float2(*(__half2*)&h01);
    float  f2  = __half2float(*(__half*)&h2);
    S1r = fmaf(ws, f01.x, S1r);
    S1g = fmaf(ws, f01.y, S1g);
    S1b = fmaf(ws, f2,   S1b);
    S2 += ws;
}

__global__ void __launch_bounds__(APPLY_THREADS, 1)
apply_kernel(const float* __restrict__ img, float* __restrict__ out) {
    extern __shared__ unsigned s_lut[];

    for (int i = threadIdx.x; i < LUTN; i += APPLY_THREADS)
        s_lut[i] = g_lutS32[i];
    __syncthreads();

    const float4* R = (const float4*)(img);
    const float4* G = (const float4*)(img + HW);
    const float4* B = (const float4*)(img + 2 * HW);
    float4* OR = (float4*)(out);
    float4* OG = (float4*)(out + HW);
    float4* OB = (float4*)(out + 2 * HW);

    const float inv_binsize = (float)((DIMD - 1) / 1.000001);

    for (int i = blockIdx.x * APPLY_THREADS + threadIdx.x; i < NG;
         i += APPLY_BLOCKS * APPLY_THREADS) {
        float4 r4 = __ldg(&R[i]), g4 = __ldg(&G[i]), b4 = __ldg(&B[i]);

        float rr[4] = {r4.x, r4.y, r4.z, r4.w};
        float gg[4] = {g4.x, g4.y, g4.z, g4.w};
        float bb[4] = {b4.x, b4.y, b4.z, b4.w};
        float ro[4], go[4], bo[4];

#pragma unroll
        for (int k = 0; k < 4; k++) {
            float rf = rr[k] * inv_binsize;
            float gf = gg[k] * inv_binsize;
            float bf = bb[k] * inv_binsize;
            int rid0 = (int)rf, gid0 = (int)gf, bid0 = (int)bf;   // floor (inputs >= 0)
            float rd = rf - (float)rid0;
            float gd = gf - (float)gid0;
            float bd = bf - (float)bid0;
            int rid = min(rid0, DIMD - 2);
            int gid = min(gid0, DIMD - 2);
            int bid = min(bid0, DIMD - 2);

            int base = (bid * 33 + gid) * 33 + rid;

            float r1g0 = rd * (1.0f - gd);
            float r0g0 = (1.0f - gd) - r1g0;   // (1-rd)(1-gd)
            float r1g1 = rd * gd;
            float r0g1 = gd - r1g1;            // (1-rd)gd

            // plane bid
            float S1r = 0.f, S1g = 0.f, S1b = 0.f, S2 = 0.f;
            corner_acc(s_lut[base],        r0g0, S1r, S1g, S1b, S2);
            corner_acc(s_lut[base + 1],    r1g0, S1r, S1g, S1b, S2);
            corner_acc(s_lut[base + 33],   r0g1, S1r, S1g, S1b, S2);
            corner_acc(s_lut[base + 34],   r1g1, S1r, S1g, S1b, S2);
            float p0r = fmaf(-1152.0f, S2, S1r);
            float p0g = fmaf(-1152.0f, S2, S1g);
            float p0b = fmaf(-1152.0f, S2, S1b);

            // plane bid+1
            float T1r = 0.f, T1g = 0.f, T1b = 0.f, T2 = 0.f;
            corner_acc(s_lut[base + 1089], r0g0, T1r, T1g, T1b, T2);
            corner_acc(s_lut[base + 1090], r1g0, T1r, T1g, T1b, T2);
            corner_acc(s_lut[base + 1122], r0g1, T1r, T1g, T1b, T2);
            corner_acc(s_lut[base + 1123], r1g1, T1r, T1g, T1b, T2);
            float p1r = fmaf(-1152.0f, T2, T1r);
            float p1g = fmaf(-1152.0f, T2, T1g);
            float p1b = fmaf(-1152.0f, T2, T1b);

            ro[k] = fmaf(bd, p1r - p0r, p0r) + rr[k];
            go[k] = fmaf(bd, p1g - p0g, p0g) + gg[k];
            bo[k] = fmaf(bd, p1b - p0b, p0b) + bb[k];
        }

        OR[i] = make_float4(ro[0], ro[1], ro[2], ro[3]);
        OG[i] = make_float4(go[0], go[1], go[2], go[3]);
        OB[i] = make_float4(bo[0], bo[1], bo[2], bo[3]);
    }
}

// ============================================================
extern "C" void kernel_launch(void* const* d_in, const int* in_sizes, int n_in,
                              void* d_out, int out_size) {
    const int*   msb      = (const int*)d_in[0];
    const int*   lsb      = (const int*)d_in[1];
    const float* img      = (const float*)d_in[2];
    const float* fm       = (const float*)d_in[3];
    const float* fl       = (const float*)d_in[4];
    const float* lut_cat  = (const float*)d_in[5];
    const float* s_layers = (const float*)d_in[6];
    const float* w_layers = (const float*)d_in[7];
    const float* luts     = (const float*)d_in[8];
    float* out = (float*)d_out;

    const int apply_smem = LUTN * 4;          // 143748
    const int lutf_smem  = NPVAL * 4;         // 65340
    cudaFuncSetAttribute(apply_kernel, cudaFuncAttributeMaxDynamicSharedMemorySize,
                         apply_smem);
    cudaFuncSetAttribute(lut_final_kernel, cudaFuncAttributeMaxDynamicSharedMemorySize,
                         lutf_smem);

    feat_kernel<<<NBLK_FEAT, 256>>>(msb, lsb, fm, fl);
    bwp_kernel<<<(NPVAL + 255) / 256, 256>>>(lut_cat, luts, w_layers);
    lut_final_kernel<<<NLBLK, 256, lutf_smem>>>(s_layers, out + 3 * HW);
    apply_kernel<<<APPLY_BLOCKS, APPLY_THREADS, apply_smem>>>(img, out);
}